// round 9
// baseline (speedup 1.0000x reference)
#include <cuda_runtime.h>
#include <cuda_fp16.h>
#include <math.h>
#include <cstdint>

// Shapes: B=64, N=1024, F=4, H=128. BN = 65536 nodes.
// Output: pi [64,1024] then v [64,1] -> 65600 floats.
#define BN 65536
#define NTILES 1024
#define GRID_LOGITS 342   // <= 148*3 slots, single wave, max 3 tiles/block

typedef unsigned long long ull;

__device__ float g_hx[128];
__device__ float g_gates[512];

// ---------------- scalar helpers ----------------
__device__ __forceinline__ float tanh_fast(float x) {
    float r; asm("tanh.approx.f32 %0, %1;" : "=f"(r) : "f"(x)); return r;
}
// ---------------- packed f32x2 helpers ----------------
__device__ __forceinline__ ull pack2(float lo, float hi) {
    ull r; asm("mov.b64 %0, {%1, %2};" : "=l"(r) : "f"(lo), "f"(hi)); return r;
}
__device__ __forceinline__ void unpack2(ull p, float& lo, float& hi) {
    asm("mov.b64 {%0, %1}, %2;" : "=f"(lo), "=f"(hi) : "l"(p));
}
__device__ __forceinline__ ull fma2(ull a, ull b, ull c) {
    ull r; asm("fma.rn.f32x2 %0, %1, %2, %3;" : "=l"(r) : "l"(a), "l"(b), "l"(c)); return r;
}
__device__ __forceinline__ ull mul2(ull a, ull b) {
    ull r; asm("mul.rn.f32x2 %0, %1, %2;" : "=l"(r) : "l"(a), "l"(b)); return r;
}
__device__ __forceinline__ ull add2(ull a, ull b) {
    ull r; asm("add.rn.f32x2 %0, %1, %2;" : "=l"(r) : "l"(a), "l"(b)); return r;
}

// ---------------------------------------------------------------------------
// Kernel 0a: gates = q . W_ih^T + b_ih + b_hh  (512 rows over 32 blocks)
// ---------------------------------------------------------------------------
__global__ void k_gates(const float* __restrict__ Wih, const float* __restrict__ bih,
                        const float* __restrict__ bhh, const float* __restrict__ q) {
    __shared__ float qs[128];
    int t = threadIdx.x;
    qs[t] = q[t];
    __syncthreads();
    int row = blockIdx.x * 16 + (t >> 3);
    int part = t & 7;
    const float4* w4 = (const float4*)(Wih + row * 128 + part * 16);
    const float4* q4 = (const float4*)(qs + part * 16);
    float s = 0.f;
    #pragma unroll
    for (int i = 0; i < 4; i++) {
        float4 w = w4[i];
        float4 qq = q4[i];
        s += w.x * qq.x + w.y * qq.y + w.z * qq.z + w.w * qq.w;
    }
    s += __shfl_xor_sync(0xffffffff, s, 1);
    s += __shfl_xor_sync(0xffffffff, s, 2);
    s += __shfl_xor_sync(0xffffffff, s, 4);
    if (part == 0) g_gates[row] = s + bih[row] + bhh[row];
}

// ---------------------------------------------------------------------------
// Kernel 0b: hx nonlinearity + v scalar. 1 block, 128 threads.
// ---------------------------------------------------------------------------
__global__ void k_hxv(const float* __restrict__ Wval, const float* __restrict__ bval,
                      float* __restrict__ out) {
    __shared__ float vred[128];
    int t = threadIdx.x;
    float ig = g_gates[t];
    float gg = g_gates[256 + t];
    float og = g_gates[384 + t];
    float si = 1.f / (1.f + __expf(-ig));
    float so = 1.f / (1.f + __expf(-og));
    float cx = si * tanh_fast(gg);
    float hx = so * tanh_fast(cx);
    g_hx[t] = hx;
    vred[t] = hx * Wval[t];
    __syncthreads();
    for (int s = 64; s > 0; s >>= 1) {
        if (t < s) vred[t] += vred[t + s];
        __syncthreads();
    }
    float v = vred[0] + bval[0];
    if (t < 64) out[BN + t] = v;
}

// ---------------------------------------------------------------------------
// Kernel 1: logits via fp16 mma.sync m16n8k16, fp32 accum. occ 3, grid 342.
// W_emb/b_emb in smem (kp-outer embedding loop) to keep regs < 170 (no spill).
// xs double-buffered; 2 syncthreads per tile.
// ---------------------------------------------------------------------------
#define AH_STRIDE 72
#define AS_OFF   0        // 128*72 half2 = 9216 floats
#define ES_OFF   9216     // 64*72 half2 = 4608 floats
#define XS_OFF   13824    // 2 x 256 floats (double-buffered float4 x 64)
#define WES_OFF  14336    // 512 (W_emb)
#define BES_OFF  14848    // 128
#define HXS_OFF  14976    // 128
#define VPS_OFF  15104    // 128
#define RED_OFF  15232    // 128
#define SM_FLOATS 15360

__global__ __launch_bounds__(128, 3)
void k_logits(const float* __restrict__ nf, const float* __restrict__ Wemb,
              const float* __restrict__ bemb, const float* __restrict__ Wattn,
              const float* __restrict__ vparam, float* __restrict__ out) {
    extern __shared__ float sm[];
    __half2* as2 = (__half2*)sm;              // [128][72]
    __half2* es2 = (__half2*)(sm + ES_OFF);   // [64][72]
    float4* xsb  = (float4*)(sm + XS_OFF);    // [2][64]
    float* wes   = sm + WES_OFF;
    float* bes   = sm + BES_OFF;
    float* hxs   = sm + HXS_OFF;
    float* vps   = sm + VPS_OFF;
    float* red   = sm + RED_OFF;

    int t = threadIdx.x;
    int lane = t & 31, w = t >> 5;
    int g = lane >> 2, tc = lane & 3;
    int wm = w >> 1, wn = w & 1;
    int hb = wm * 64, nb_w = wn * 32;

    // ---- one-time staging: A = half2(W_attn), permuted k-pair columns ----
    for (int i = t * 4; i < 16384; i += 512) {
        float4 wv = *(const float4*)(Wattn + i);
        int h = i >> 7, k = i & 127;
        int k2 = k >> 1;
        int kb8 = k2 & ~7, j = k2 & 7;       // j in {0,2,4,6}
        int c1 = kb8 + ((j < 4) ? 2 * j : 2 * j - 7);
        as2[h * AH_STRIDE + c1]     = __floats2half2_rn(wv.x, wv.y);
        as2[h * AH_STRIDE + c1 + 2] = __floats2half2_rn(wv.z, wv.w);
    }
    for (int i = t; i < 512; i += 128) wes[i] = Wemb[i];
    bes[t] = bemb[t];
    hxs[t] = g_hx[t];
    vps[t] = vparam[t];

    // per-thread tile geometry: k2 quartet K0..K0+3, node octet
    int K0 = (t >> 3) * 4;
    int nodeb = (t & 7) * 8;
    int cols[4];
    #pragma unroll
    for (int kp = 0; kp < 4; kp++) {
        int k2v = K0 + kp;
        int j = k2v & 7;
        cols[kp] = (k2v & ~7) + ((j < 4) ? 2 * j : 2 * j - 7);
    }

    const ull C3 = pack2(-0.3333333333f, -0.3333333333f);
    const ull C5 = pack2(0.1333333333f, 0.1333333333f);
    const ull C7 = pack2(-0.0539682540f, -0.0539682540f);
    const __half2 hzero = __floats2half2_rn(0.f, 0.f);

    // preload xs for first tile
    int tile0 = blockIdx.x;
    if (t < 64 && tile0 < NTILES)
        xsb[t] = __ldg((const float4*)nf + (tile0 * 64 + t));
    __syncthreads();

    int buf = 0;
    for (int tile = tile0; tile < NTILES; tile += GRID_LOGITS) {
        int base = tile * 64;
        const float4* xs = xsb + buf * 64;

        // ---- embedding: kp outer (weights cached in regs per kp) ----
        #pragma unroll
        for (int kp = 0; kp < 4; kp++) {
            int kk = 2 * (K0 + kp);
            float4 wa = *(const float4*)&wes[kk * 4];       // W_emb row kk
            float4 wb = *(const float4*)&wes[(kk + 1) * 4]; // row kk+1
            float bl = bes[kk], bh = bes[kk + 1];
            __half2* dstc = es2 + cols[kp];
            #pragma unroll
            for (int nn = 0; nn < 8; nn++) {
                int n = nodeb + ((nn + (t >> 3)) & 7);
                float4 x = xs[n];
                float elo = bl + x.x * wa.x + x.y * wa.y + x.z * wa.z + x.w * wa.w;
                float ehi = bh + x.x * wb.x + x.y * wb.y + x.z * wb.z + x.w * wb.w;
                dstc[n * AH_STRIDE] = __hmax2(__floats2half2_rn(elo, ehi), hzero);
            }
        }
        __syncthreads();   // es ready

        // prefetch next tile's xs into the other buffer
        int nxt = tile + GRID_LOGITS;
        if (t < 64 && nxt < NTILES)
            xsb[(buf ^ 1) * 64 + t] = __ldg((const float4*)nf + (nxt * 64 + t));

        // ---- fp16 tensor GEMM: C[h][n], warp tile 64x32, K chunks of 16 ----
        float accr[4][4][4];
        #pragma unroll
        for (int mi = 0; mi < 4; mi++)
            #pragma unroll
            for (int ni = 0; ni < 4; ni++)
                #pragma unroll
                for (int j = 0; j < 4; j++) accr[mi][ni][j] = 0.f;

        #pragma unroll
        for (int kt = 0; kt < 8; kt++) {
            int cb = kt * 8 + 2 * tc;
            uint2 alo[4], ahi[4];
            #pragma unroll
            for (int mi = 0; mi < 4; mi++) {
                int r = hb + mi * 16 + g;
                alo[mi] = *(const uint2*)(as2 + r * AH_STRIDE + cb);
                ahi[mi] = *(const uint2*)(as2 + (r + 8) * AH_STRIDE + cb);
            }
            uint2 bfr[4];
            #pragma unroll
            for (int ni = 0; ni < 4; ni++) {
                int n = nb_w + ni * 8 + g;
                bfr[ni] = *(const uint2*)(es2 + n * AH_STRIDE + cb);
            }
            #pragma unroll
            for (int mi = 0; mi < 4; mi++)
                #pragma unroll
                for (int ni = 0; ni < 4; ni++) {
                    asm volatile(
                        "mma.sync.aligned.m16n8k16.row.col.f32.f16.f16.f32 "
                        "{%0,%1,%2,%3}, {%4,%5,%6,%7}, {%8,%9}, {%0,%1,%2,%3};"
                        : "+f"(accr[mi][ni][0]), "+f"(accr[mi][ni][1]),
                          "+f"(accr[mi][ni][2]), "+f"(accr[mi][ni][3])
                        : "r"(alo[mi].x), "r"(ahi[mi].x),
                          "r"(alo[mi].y), "r"(ahi[mi].y),
                          "r"(bfr[ni].x), "r"(bfr[ni].y));
                }
        }

        // ---- dual-pipe epilogue (MUFU + packed poly), reduce over h ----
        ull s2[4];
        #pragma unroll
        for (int ni = 0; ni < 4; ni++) s2[ni] = pack2(0.f, 0.f);

        #pragma unroll
        for (int mi = 0; mi < 4; mi++) {
            int h0 = hb + mi * 16 + g;
            ull hxa = pack2(hxs[h0], hxs[h0]);
            ull hxb = pack2(hxs[h0 + 8], hxs[h0 + 8]);
            ull va  = pack2(vps[h0], vps[h0]);
            ull vb  = pack2(vps[h0 + 8], vps[h0 + 8]);
            #pragma unroll
            for (int ni = 0; ni < 4; ni++) {
                ull pa = pack2(accr[mi][ni][0], accr[mi][ni][1]);
                ull pb = pack2(accr[mi][ni][2], accr[mi][ni][3]);
                ull ya = add2(pa, hxa);
                ull yb = add2(pb, hxb);
                if (mi < 2) {
                    float l0, l1;
                    unpack2(ya, l0, l1);
                    ull ta = pack2(tanh_fast(l0), tanh_fast(l1));
                    s2[ni] = fma2(va, ta, s2[ni]);
                    unpack2(yb, l0, l1);
                    ull tb = pack2(tanh_fast(l0), tanh_fast(l1));
                    s2[ni] = fma2(vb, tb, s2[ni]);
                } else {
                    ull ua = mul2(ya, ya);
                    ull qa = fma2(ua, C7, C5);
                    qa = fma2(ua, qa, C3);
                    ull wa = mul2(ya, ua);
                    ull ta = fma2(wa, qa, ya);
                    s2[ni] = fma2(va, ta, s2[ni]);

                    ull ub = mul2(yb, yb);
                    ull qb = fma2(ub, C7, C5);
                    qb = fma2(ub, qb, C3);
                    ull wb = mul2(yb, ub);
                    ull tb = fma2(wb, qb, yb);
                    s2[ni] = fma2(vb, tb, s2[ni]);
                }
            }
        }

        float pl[4][2];
        #pragma unroll
        for (int ni = 0; ni < 4; ni++) unpack2(s2[ni], pl[ni][0], pl[ni][1]);

        #pragma unroll
        for (int off = 4; off < 32; off <<= 1)
            #pragma unroll
            for (int ni = 0; ni < 4; ni++)
                #pragma unroll
                for (int j = 0; j < 2; j++)
                    pl[ni][j] += __shfl_xor_sync(0xffffffff, pl[ni][j], off);
        if (g == 0) {
            #pragma unroll
            for (int ni = 0; ni < 4; ni++)
                #pragma unroll
                for (int j = 0; j < 2; j++)
                    red[(nb_w + ni * 8 + 2 * tc + j) * 2 + wm] = pl[ni][j];
        }
        __syncthreads();   // red ready; es free; xs[next] ready
        if (t < 64) out[base + t] = red[t * 2] + red[t * 2 + 1];
        buf ^= 1;
    }
}

// ---------------------------------------------------------------------------
// Kernel 2: softmax over N=1024 per batch, in place. Warp-shuffle reductions.
// ---------------------------------------------------------------------------
__global__ void k_softmax(float* __restrict__ out) {
    __shared__ float wred[8];
    __shared__ float bcast[2];
    int b = blockIdx.x;
    int t = threadIdx.x;
    int lane = t & 31, wid = t >> 5;
    float* row = out + b * 1024;
    float4 x = ((const float4*)row)[t];
    float m = fmaxf(fmaxf(x.x, x.y), fmaxf(x.z, x.w));
    #pragma unroll
    for (int o = 16; o > 0; o >>= 1)
        m = fmaxf(m, __shfl_xor_sync(0xffffffff, m, o));
    if (lane == 0) wred[wid] = m;
    __syncthreads();
    if (wid == 0) {
        float mm = wred[lane & 7];
        #pragma unroll
        for (int o = 4; o > 0; o >>= 1)
            mm = fmaxf(mm, __shfl_xor_sync(0xffffffff, mm, o));
        if (lane == 0) bcast[0] = mm;
    }
    __syncthreads();
    float M = bcast[0];
    float e0 = __expf(x.x - M);
    float e1 = __expf(x.y - M);
    float e2 = __expf(x.z - M);
    float e3 = __expf(x.w - M);
    float s = e0 + e1 + e2 + e3;
    #pragma unroll
    for (int o = 16; o > 0; o >>= 1)
        s += __shfl_xor_sync(0xffffffff, s, o);
    if (lane == 0) wred[wid] = s;
    __syncthreads();
    if (wid == 0) {
        float ss = wred[lane & 7];
        #pragma unroll
        for (int o = 4; o > 0; o >>= 1)
            ss += __shfl_xor_sync(0xffffffff, ss, o);
        if (lane == 0) bcast[1] = ss;
    }
    __syncthreads();
    float inv = 1.f / bcast[1];
    float4 r;
    r.x = e0 * inv; r.y = e1 * inv; r.z = e2 * inv; r.w = e3 * inv;
    ((float4*)row)[t] = r;
}

// ---------------------------------------------------------------------------
extern "C" void kernel_launch(void* const* d_in, const int* in_sizes, int n_in,
                              void* d_out, int out_size) {
    const float* nf     = (const float*)d_in[0];
    const float* Wemb   = (const float*)d_in[2];
    const float* bemb   = (const float*)d_in[3];
    const float* Wih    = (const float*)d_in[4];
    const float* bih    = (const float*)d_in[5];
    const float* bhh    = (const float*)d_in[7];
    const float* query  = (const float*)d_in[8];
    const float* Wattn  = (const float*)d_in[9];
    const float* vparam = (const float*)d_in[10];
    const float* Wval   = (const float*)d_in[11];
    const float* bval   = (const float*)d_in[12];
    float* out = (float*)d_out;

    static int smem_set = 0;
    const int smem_bytes = SM_FLOATS * 4;
    if (!smem_set) {
        cudaFuncSetAttribute(k_logits, cudaFuncAttributeMaxDynamicSharedMemorySize,
                             smem_bytes);
        smem_set = 1;
    }

    k_gates<<<32, 128>>>(Wih, bih, bhh, query);
    k_hxv<<<1, 128>>>(Wval, bval, out);
    k_logits<<<GRID_LOGITS, 128, smem_bytes>>>(nf, Wemb, bemb, Wattn, vparam, out);
    k_softmax<<<64, 256>>>(out);
}

// round 10
// speedup vs baseline: 1.5988x; 1.5988x over previous
#include <cuda_runtime.h>
#include <cuda_fp16.h>
#include <math.h>
#include <cstdint>

// Shapes: B=64, N=1024, F=4, H=128. BN = 65536 nodes.
// Output: pi [64,1024] then v [64,1] -> 65600 floats.
#define BN 65536
#define NTILES 1024
#define GRID_LOGITS 296   // 148 SMs x 2 CTAs (occ 2 => 256 regs/thread budget)

typedef unsigned long long ull;

__device__ float g_hx[128];
__device__ float g_gates[512];

// ---------------- scalar helpers ----------------
__device__ __forceinline__ float tanh_fast(float x) {
    float r; asm("tanh.approx.f32 %0, %1;" : "=f"(r) : "f"(x)); return r;
}
// ---------------- packed f32x2 helpers ----------------
__device__ __forceinline__ ull pack2(float lo, float hi) {
    ull r; asm("mov.b64 %0, {%1, %2};" : "=l"(r) : "f"(lo), "f"(hi)); return r;
}
__device__ __forceinline__ void unpack2(ull p, float& lo, float& hi) {
    asm("mov.b64 {%0, %1}, %2;" : "=f"(lo), "=f"(hi) : "l"(p));
}
__device__ __forceinline__ ull fma2(ull a, ull b, ull c) {
    ull r; asm("fma.rn.f32x2 %0, %1, %2, %3;" : "=l"(r) : "l"(a), "l"(b), "l"(c)); return r;
}
__device__ __forceinline__ ull mul2(ull a, ull b) {
    ull r; asm("mul.rn.f32x2 %0, %1, %2;" : "=l"(r) : "l"(a), "l"(b)); return r;
}
__device__ __forceinline__ ull add2(ull a, ull b) {
    ull r; asm("add.rn.f32x2 %0, %1, %2;" : "=l"(r) : "l"(a), "l"(b)); return r;
}

// ---------------------------------------------------------------------------
// Kernel 0a: gates = q . W_ih^T + b_ih + b_hh  (512 rows over 32 blocks)
// ---------------------------------------------------------------------------
__global__ void k_gates(const float* __restrict__ Wih, const float* __restrict__ bih,
                        const float* __restrict__ bhh, const float* __restrict__ q) {
    __shared__ float qs[128];
    int t = threadIdx.x;
    qs[t] = q[t];
    __syncthreads();
    int row = blockIdx.x * 16 + (t >> 3);
    int part = t & 7;
    const float4* w4 = (const float4*)(Wih + row * 128 + part * 16);
    const float4* q4 = (const float4*)(qs + part * 16);
    float s = 0.f;
    #pragma unroll
    for (int i = 0; i < 4; i++) {
        float4 w = w4[i];
        float4 qq = q4[i];
        s += w.x * qq.x + w.y * qq.y + w.z * qq.z + w.w * qq.w;
    }
    s += __shfl_xor_sync(0xffffffff, s, 1);
    s += __shfl_xor_sync(0xffffffff, s, 2);
    s += __shfl_xor_sync(0xffffffff, s, 4);
    if (part == 0) g_gates[row] = s + bih[row] + bhh[row];
}

// ---------------------------------------------------------------------------
// Kernel 0b: hx nonlinearity + v scalar. 1 block, 128 threads.
// ---------------------------------------------------------------------------
__global__ void k_hxv(const float* __restrict__ Wval, const float* __restrict__ bval,
                      float* __restrict__ out) {
    __shared__ float vred[128];
    int t = threadIdx.x;
    float ig = g_gates[t];
    float gg = g_gates[256 + t];
    float og = g_gates[384 + t];
    float si = 1.f / (1.f + __expf(-ig));
    float so = 1.f / (1.f + __expf(-og));
    float cx = si * tanh_fast(gg);
    float hx = so * tanh_fast(cx);
    g_hx[t] = hx;
    vred[t] = hx * Wval[t];
    __syncthreads();
    for (int s = 64; s > 0; s >>= 1) {
        if (t < s) vred[t] += vred[t + s];
        __syncthreads();
    }
    float v = vred[0] + bval[0];
    if (t < 64) out[BN + t] = v;
}

// ---------------------------------------------------------------------------
// Kernel 1: logits via fp16 mma.sync m16n8k16, fp32 accum.
// R7 config (occ 2, grid 296, register W_emb cache) + xs double-buffer
// prefetch (2 barriers/tile).
// ---------------------------------------------------------------------------
#define AH_STRIDE 72
#define AS_OFF   0        // 128*72 half2 = 9216 floats
#define ES_OFF   9216     // 64*72 half2 = 4608 floats
#define XS_OFF   13824    // 2 x 256 floats (double-buffered float4 x 64)
#define HXS_OFF  14336    // 128
#define VPS_OFF  14464    // 128
#define RED_OFF  14592    // 128
#define SM_FLOATS 14720

__global__ __launch_bounds__(128, 2)
void k_logits(const float* __restrict__ nf, const float* __restrict__ Wemb,
              const float* __restrict__ bemb, const float* __restrict__ Wattn,
              const float* __restrict__ vparam, float* __restrict__ out) {
    extern __shared__ float sm[];
    __half2* as2 = (__half2*)sm;              // [128][72]
    __half2* es2 = (__half2*)(sm + ES_OFF);   // [64][72]
    float4* xsb  = (float4*)(sm + XS_OFF);    // [2][64]
    float* hxs   = sm + HXS_OFF;
    float* vps   = sm + VPS_OFF;
    float* red   = sm + RED_OFF;

    int t = threadIdx.x;
    int lane = t & 31, w = t >> 5;
    int g = lane >> 2, tc = lane & 3;
    int wm = w >> 1, wn = w & 1;
    int hb = wm * 64, nb_w = wn * 32;

    // ---- one-time staging: A = half2(W_attn), permuted k-pair columns ----
    for (int i = t * 4; i < 16384; i += 512) {
        float4 wv = *(const float4*)(Wattn + i);
        int h = i >> 7, k = i & 127;
        int k2 = k >> 1;
        int kb8 = k2 & ~7, j = k2 & 7;       // j in {0,2,4,6}
        int c1 = kb8 + ((j < 4) ? 2 * j : 2 * j - 7);
        as2[h * AH_STRIDE + c1]     = __floats2half2_rn(wv.x, wv.y);
        as2[h * AH_STRIDE + c1 + 2] = __floats2half2_rn(wv.z, wv.w);
    }
    hxs[t] = g_hx[t];
    vps[t] = vparam[t];

    // ---- per-thread embedding weights: k2 quartet K0..K0+3, node octet ----
    int K0 = (t >> 3) * 4;
    int nodeb = (t & 7) * 8;
    ull w2[16], b2[4];
    int cols[4];
    #pragma unroll
    for (int kp = 0; kp < 4; kp++) {
        int k2v = K0 + kp;
        int kk = 2 * k2v;
        #pragma unroll
        for (int f = 0; f < 4; f++)
            w2[kp * 4 + f] = pack2(Wemb[kk * 4 + f], Wemb[(kk + 1) * 4 + f]);
        b2[kp] = pack2(bemb[kk], bemb[kk + 1]);
        int j = k2v & 7;
        cols[kp] = (k2v & ~7) + ((j < 4) ? 2 * j : 2 * j - 7);
    }

    const ull C3 = pack2(-0.3333333333f, -0.3333333333f);
    const ull C5 = pack2(0.1333333333f, 0.1333333333f);
    const ull C7 = pack2(-0.0539682540f, -0.0539682540f);
    const __half2 hzero = __floats2half2_rn(0.f, 0.f);

    // preload xs for first tile
    int tile0 = blockIdx.x;
    if (t < 64 && tile0 < NTILES)
        xsb[t] = __ldg((const float4*)nf + (tile0 * 64 + t));
    __syncthreads();

    int buf = 0;
    for (int tile = tile0; tile < NTILES; tile += GRID_LOGITS) {
        int base = tile * 64;
        const float4* xs = xsb + buf * 64;

        // ---- embedding: es2[n][col(kp)] = half2(relu pair), nn-outer ----
        #pragma unroll
        for (int nn = 0; nn < 8; nn++) {
            int n = nodeb + ((nn + (t >> 3)) & 7);
            float4 x = xs[n];
            ull x0 = pack2(x.x, x.x), x1 = pack2(x.y, x.y);
            ull x2 = pack2(x.z, x.z), x3 = pack2(x.w, x.w);
            __half2* dst = es2 + n * AH_STRIDE;
            #pragma unroll
            for (int kp = 0; kp < 4; kp++) {
                ull e = b2[kp];
                e = fma2(x0, w2[kp * 4 + 0], e);
                e = fma2(x1, w2[kp * 4 + 1], e);
                e = fma2(x2, w2[kp * 4 + 2], e);
                e = fma2(x3, w2[kp * 4 + 3], e);
                float lo, hi;
                unpack2(e, lo, hi);
                dst[cols[kp]] = __hmax2(__floats2half2_rn(lo, hi), hzero);
            }
        }
        __syncthreads();   // es ready

        // prefetch next tile's xs into the other buffer
        int nxt = tile + GRID_LOGITS;
        if (t < 64 && nxt < NTILES)
            xsb[(buf ^ 1) * 64 + t] = __ldg((const float4*)nf + (nxt * 64 + t));

        // ---- fp16 tensor GEMM: C[h][n], warp tile 64x32, K chunks of 16 ----
        float accr[4][4][4];
        #pragma unroll
        for (int mi = 0; mi < 4; mi++)
            #pragma unroll
            for (int ni = 0; ni < 4; ni++)
                #pragma unroll
                for (int j = 0; j < 4; j++) accr[mi][ni][j] = 0.f;

        #pragma unroll
        for (int kt = 0; kt < 8; kt++) {
            int cb = kt * 8 + 2 * tc;
            uint2 alo[4], ahi[4];
            #pragma unroll
            for (int mi = 0; mi < 4; mi++) {
                int r = hb + mi * 16 + g;
                alo[mi] = *(const uint2*)(as2 + r * AH_STRIDE + cb);
                ahi[mi] = *(const uint2*)(as2 + (r + 8) * AH_STRIDE + cb);
            }
            uint2 bfr[4];
            #pragma unroll
            for (int ni = 0; ni < 4; ni++) {
                int n = nb_w + ni * 8 + g;
                bfr[ni] = *(const uint2*)(es2 + n * AH_STRIDE + cb);
            }
            #pragma unroll
            for (int mi = 0; mi < 4; mi++)
                #pragma unroll
                for (int ni = 0; ni < 4; ni++) {
                    asm volatile(
                        "mma.sync.aligned.m16n8k16.row.col.f32.f16.f16.f32 "
                        "{%0,%1,%2,%3}, {%4,%5,%6,%7}, {%8,%9}, {%0,%1,%2,%3};"
                        : "+f"(accr[mi][ni][0]), "+f"(accr[mi][ni][1]),
                          "+f"(accr[mi][ni][2]), "+f"(accr[mi][ni][3])
                        : "r"(alo[mi].x), "r"(ahi[mi].x),
                          "r"(alo[mi].y), "r"(ahi[mi].y),
                          "r"(bfr[ni].x), "r"(bfr[ni].y));
                }
        }

        // ---- dual-pipe epilogue (MUFU + packed poly), reduce over h ----
        ull s2[4];
        #pragma unroll
        for (int ni = 0; ni < 4; ni++) s2[ni] = pack2(0.f, 0.f);

        #pragma unroll
        for (int mi = 0; mi < 4; mi++) {
            int h0 = hb + mi * 16 + g;
            ull hxa = pack2(hxs[h0], hxs[h0]);
            ull hxb = pack2(hxs[h0 + 8], hxs[h0 + 8]);
            ull va  = pack2(vps[h0], vps[h0]);
            ull vb  = pack2(vps[h0 + 8], vps[h0 + 8]);
            #pragma unroll
            for (int ni = 0; ni < 4; ni++) {
                ull pa = pack2(accr[mi][ni][0], accr[mi][ni][1]);
                ull pb = pack2(accr[mi][ni][2], accr[mi][ni][3]);
                ull ya = add2(pa, hxa);
                ull yb = add2(pb, hxb);
                if (mi < 2) {
                    float l0, l1;
                    unpack2(ya, l0, l1);
                    ull ta = pack2(tanh_fast(l0), tanh_fast(l1));
                    s2[ni] = fma2(va, ta, s2[ni]);
                    unpack2(yb, l0, l1);
                    ull tb = pack2(tanh_fast(l0), tanh_fast(l1));
                    s2[ni] = fma2(vb, tb, s2[ni]);
                } else {
                    ull ua = mul2(ya, ya);
                    ull qa = fma2(ua, C7, C5);
                    qa = fma2(ua, qa, C3);
                    ull wa = mul2(ya, ua);
                    ull ta = fma2(wa, qa, ya);
                    s2[ni] = fma2(va, ta, s2[ni]);

                    ull ub = mul2(yb, yb);
                    ull qb = fma2(ub, C7, C5);
                    qb = fma2(ub, qb, C3);
                    ull wb = mul2(yb, ub);
                    ull tb = fma2(wb, qb, yb);
                    s2[ni] = fma2(vb, tb, s2[ni]);
                }
            }
        }

        float pl[4][2];
        #pragma unroll
        for (int ni = 0; ni < 4; ni++) unpack2(s2[ni], pl[ni][0], pl[ni][1]);

        #pragma unroll
        for (int off = 4; off < 32; off <<= 1)
            #pragma unroll
            for (int ni = 0; ni < 4; ni++)
                #pragma unroll
                for (int j = 0; j < 2; j++)
                    pl[ni][j] += __shfl_xor_sync(0xffffffff, pl[ni][j], off);
        if (g == 0) {
            #pragma unroll
            for (int ni = 0; ni < 4; ni++)
                #pragma unroll
                for (int j = 0; j < 2; j++)
                    red[(nb_w + ni * 8 + 2 * tc + j) * 2 + wm] = pl[ni][j];
        }
        __syncthreads();   // red ready; es free; xs[next] ready
        if (t < 64) out[base + t] = red[t * 2] + red[t * 2 + 1];
        buf ^= 1;
    }
}

// ---------------------------------------------------------------------------
// Kernel 2: softmax over N=1024 per batch, in place. Warp-shuffle reductions.
// ---------------------------------------------------------------------------
__global__ void k_softmax(float* __restrict__ out) {
    __shared__ float wred[8];
    __shared__ float bcast[2];
    int b = blockIdx.x;
    int t = threadIdx.x;
    int lane = t & 31, wid = t >> 5;
    float* row = out + b * 1024;
    float4 x = ((const float4*)row)[t];
    float m = fmaxf(fmaxf(x.x, x.y), fmaxf(x.z, x.w));
    #pragma unroll
    for (int o = 16; o > 0; o >>= 1)
        m = fmaxf(m, __shfl_xor_sync(0xffffffff, m, o));
    if (lane == 0) wred[wid] = m;
    __syncthreads();
    if (wid == 0) {
        float mm = wred[lane & 7];
        #pragma unroll
        for (int o = 4; o > 0; o >>= 1)
            mm = fmaxf(mm, __shfl_xor_sync(0xffffffff, mm, o));
        if (lane == 0) bcast[0] = mm;
    }
    __syncthreads();
    float M = bcast[0];
    float e0 = __expf(x.x - M);
    float e1 = __expf(x.y - M);
    float e2 = __expf(x.z - M);
    float e3 = __expf(x.w - M);
    float s = e0 + e1 + e2 + e3;
    #pragma unroll
    for (int o = 16; o > 0; o >>= 1)
        s += __shfl_xor_sync(0xffffffff, s, o);
    if (lane == 0) wred[wid] = s;
    __syncthreads();
    if (wid == 0) {
        float ss = wred[lane & 7];
        #pragma unroll
        for (int o = 4; o > 0; o >>= 1)
            ss += __shfl_xor_sync(0xffffffff, ss, o);
        if (lane == 0) bcast[1] = ss;
    }
    __syncthreads();
    float inv = 1.f / bcast[1];
    float4 r;
    r.x = e0 * inv; r.y = e1 * inv; r.z = e2 * inv; r.w = e3 * inv;
    ((float4*)row)[t] = r;
}

// ---------------------------------------------------------------------------
extern "C" void kernel_launch(void* const* d_in, const int* in_sizes, int n_in,
                              void* d_out, int out_size) {
    const float* nf     = (const float*)d_in[0];
    const float* Wemb   = (const float*)d_in[2];
    const float* bemb   = (const float*)d_in[3];
    const float* Wih    = (const float*)d_in[4];
    const float* bih    = (const float*)d_in[5];
    const float* bhh    = (const float*)d_in[7];
    const float* query  = (const float*)d_in[8];
    const float* Wattn  = (const float*)d_in[9];
    const float* vparam = (const float*)d_in[10];
    const float* Wval   = (const float*)d_in[11];
    const float* bval   = (const float*)d_in[12];
    float* out = (float*)d_out;

    static int smem_set = 0;
    const int smem_bytes = SM_FLOATS * 4;
    if (!smem_set) {
        cudaFuncSetAttribute(k_logits, cudaFuncAttributeMaxDynamicSharedMemorySize,
                             smem_bytes);
        smem_set = 1;
    }

    k_gates<<<32, 128>>>(Wih, bih, bhh, query);
    k_hxv<<<1, 128>>>(Wval, bval, out);
    k_logits<<<GRID_LOGITS, 128, smem_bytes>>>(nf, Wemb, bemb, Wattn, vparam, out);
    k_softmax<<<64, 256>>>(out);
}

// round 12
// speedup vs baseline: 1.9013x; 1.1892x over previous
#include <cuda_runtime.h>
#include <cuda_fp16.h>
#include <math.h>
#include <cstdint>

// Shapes: B=64, N=1024, F=4, H=128. BN = 65536 nodes.
// Output: pi [64,1024] then v [64,1] -> 65600 floats.
#define BN 65536
#define NT16 4096          // 16-node tiles
#define GRID_LOGITS 256    // x4 warps = 1024 warp-tiles -> exactly 4 tiles/warp

typedef unsigned long long ull;

__device__ float g_hx[128];
__device__ float g_gates[512];

// ---------------- scalar helpers ----------------
__device__ __forceinline__ float tanh_fast(float x) {
    float r; asm("tanh.approx.f32 %0, %1;" : "=f"(r) : "f"(x)); return r;
}
// ---------------- packed f32x2 helpers ----------------
__device__ __forceinline__ ull pack2(float lo, float hi) {
    ull r; asm("mov.b64 %0, {%1, %2};" : "=l"(r) : "f"(lo), "f"(hi)); return r;
}
__device__ __forceinline__ void unpack2(ull p, float& lo, float& hi) {
    asm("mov.b64 {%0, %1}, %2;" : "=f"(lo), "=f"(hi) : "l"(p));
}
__device__ __forceinline__ ull fma2(ull a, ull b, ull c) {
    ull r; asm("fma.rn.f32x2 %0, %1, %2, %3;" : "=l"(r) : "l"(a), "l"(b), "l"(c)); return r;
}
__device__ __forceinline__ ull mul2(ull a, ull b) {
    ull r; asm("mul.rn.f32x2 %0, %1, %2;" : "=l"(r) : "l"(a), "l"(b)); return r;
}
__device__ __forceinline__ ull add2(ull a, ull b) {
    ull r; asm("add.rn.f32x2 %0, %1, %2;" : "=l"(r) : "l"(a), "l"(b)); return r;
}

// ---------------------------------------------------------------------------
// Kernel 0a: gates = q . W_ih^T + b_ih + b_hh  (512 rows over 32 blocks)
// ---------------------------------------------------------------------------
__global__ void k_gates(const float* __restrict__ Wih, const float* __restrict__ bih,
                        const float* __restrict__ bhh, const float* __restrict__ q) {
    __shared__ float qs[128];
    int t = threadIdx.x;
    qs[t] = q[t];
    __syncthreads();
    int row = blockIdx.x * 16 + (t >> 3);
    int part = t & 7;
    const float4* w4 = (const float4*)(Wih + row * 128 + part * 16);
    const float4* q4 = (const float4*)(qs + part * 16);
    float s = 0.f;
    #pragma unroll
    for (int i = 0; i < 4; i++) {
        float4 w = w4[i];
        float4 qq = q4[i];
        s += w.x * qq.x + w.y * qq.y + w.z * qq.z + w.w * qq.w;
    }
    s += __shfl_xor_sync(0xffffffff, s, 1);
    s += __shfl_xor_sync(0xffffffff, s, 2);
    s += __shfl_xor_sync(0xffffffff, s, 4);
    if (part == 0) g_gates[row] = s + bih[row] + bhh[row];
}

// ---------------------------------------------------------------------------
// Kernel 0b: hx nonlinearity + v scalar. 1 block, 128 threads.
// ---------------------------------------------------------------------------
__global__ void k_hxv(const float* __restrict__ Wval, const float* __restrict__ bval,
                      float* __restrict__ out) {
    __shared__ float vred[128];
    int t = threadIdx.x;
    float ig = g_gates[t];
    float gg = g_gates[256 + t];
    float og = g_gates[384 + t];
    float si = 1.f / (1.f + __expf(-ig));
    float so = 1.f / (1.f + __expf(-og));
    float cx = si * tanh_fast(gg);
    float hx = so * tanh_fast(cx);
    g_hx[t] = hx;
    vred[t] = hx * Wval[t];
    __syncthreads();
    for (int s = 64; s > 0; s >>= 1) {
        if (t < s) vred[t] += vred[t + s];
        __syncthreads();
    }
    float v = vred[0] + bval[0];
    if (t < 64) out[BN + t] = v;
}

// ---------------------------------------------------------------------------
// Kernel 1: logits, WARP-AUTONOMOUS tiles. Each warp owns a 16-node x 128-h
// tile: warp-private es/xs, only __syncwarp in the loop.
// Each lane covers TWO k2 pairs (lane and lane+32) => all 64 k2 cols filled.
// fp16 mma.sync m16n8k16 (mi=0..7, ni=0..1), fp32 accum.
// ---------------------------------------------------------------------------
#define AH_STRIDE 72
#define AS_OFF   0        // 128*72 half2 = 9216 float-slots
#define ES_OFF   9216     // 4 warps x 16*72 half2 = 4608
#define XS_OFF   13824    // 4 warps x 16 float4 = 256
#define HXS_OFF  14080    // 128
#define VPS_OFF  14208    // 128
#define SM_FLOATS 14336

__global__ __launch_bounds__(128, 2)
void k_logits(const float* __restrict__ nf, const float* __restrict__ Wemb,
              const float* __restrict__ bemb, const float* __restrict__ Wattn,
              const float* __restrict__ vparam, float* __restrict__ out) {
    extern __shared__ float sm[];
    __half2* as2 = (__half2*)sm;              // [128][72]
    float* hxs   = sm + HXS_OFF;
    float* vps   = sm + VPS_OFF;

    int t = threadIdx.x;
    int lane = t & 31, w = t >> 5;
    int g = lane >> 2, tc = lane & 3;

    __half2* esw = (__half2*)(sm + ES_OFF) + w * (16 * AH_STRIDE);
    float4*  xsw = (float4*)(sm + XS_OFF) + w * 16;

    // ---- one-time staging: A = half2(W_attn), permuted k-pair columns ----
    for (int i = t * 4; i < 16384; i += 512) {
        float4 wv = *(const float4*)(Wattn + i);
        int h = i >> 7, k = i & 127;
        int k2 = k >> 1;
        int kb8 = k2 & ~7, j = k2 & 7;       // j in {0,2,4,6}
        int c1 = kb8 + ((j < 4) ? 2 * j : 2 * j - 7);
        as2[h * AH_STRIDE + c1]     = __floats2half2_rn(wv.x, wv.y);
        as2[h * AH_STRIDE + c1 + 2] = __floats2half2_rn(wv.z, wv.w);
    }
    hxs[t] = g_hx[t];
    vps[t] = vparam[t];

    // ---- per-lane embedding weights: TWO k2 pairs (lane, lane+32) ----
    ull w2[8], b2[2];
    int colL[2];
    #pragma unroll
    for (int p = 0; p < 2; p++) {
        int k2v = lane + p * 32;
        int kk = 2 * k2v;
        #pragma unroll
        for (int f = 0; f < 4; f++)
            w2[p * 4 + f] = pack2(Wemb[kk * 4 + f], Wemb[(kk + 1) * 4 + f]);
        b2[p] = pack2(bemb[kk], bemb[kk + 1]);
        int j = k2v & 7;
        colL[p] = (k2v & ~7) + ((j < 4) ? 2 * j : 2 * j - 7);
    }

    const ull C3 = pack2(-0.3333333333f, -0.3333333333f);
    const ull C5 = pack2(0.1333333333f, 0.1333333333f);
    const ull C7 = pack2(-0.0539682540f, -0.0539682540f);
    const __half2 hzero = __floats2half2_rn(0.f, 0.f);

    __syncthreads();   // as2 / hxs / vps ready (only block-wide sync)

    int gw = blockIdx.x * 4 + w;       // global warp id: 0..1023
    for (int tile = gw; tile < NT16; tile += GRID_LOGITS * 4) {
        int base = tile * 16;

        // ---- warp-private xs load (16 nodes) ----
        if (lane < 16)
            xsw[lane] = __ldg((const float4*)nf + (base + lane));
        __syncwarp();

        // ---- embedding: lane fills its two k2 columns for all 16 nodes ----
        #pragma unroll
        for (int n = 0; n < 16; n++) {
            float4 x = xsw[n];
            ull x0 = pack2(x.x, x.x), x1 = pack2(x.y, x.y);
            ull x2 = pack2(x.z, x.z), x3 = pack2(x.w, x.w);
            #pragma unroll
            for (int p = 0; p < 2; p++) {
                ull e = b2[p];
                e = fma2(x0, w2[p * 4 + 0], e);
                e = fma2(x1, w2[p * 4 + 1], e);
                e = fma2(x2, w2[p * 4 + 2], e);
                e = fma2(x3, w2[p * 4 + 3], e);
                float lo, hi;
                unpack2(e, lo, hi);
                esw[n * AH_STRIDE + colL[p]] =
                    __hmax2(__floats2half2_rn(lo, hi), hzero);
            }
        }
        __syncwarp();

        // ---- fp16 GEMM: warp tile 128h x 16n, K chunks of 16 ----
        float accr[8][2][4];
        #pragma unroll
        for (int mi = 0; mi < 8; mi++)
            #pragma unroll
            for (int ni = 0; ni < 2; ni++)
                #pragma unroll
                for (int j = 0; j < 4; j++) accr[mi][ni][j] = 0.f;

        #pragma unroll
        for (int kt = 0; kt < 8; kt++) {
            int cb = kt * 8 + 2 * tc;
            uint2 bfr[2];
            #pragma unroll
            for (int ni = 0; ni < 2; ni++) {
                int n = ni * 8 + g;
                bfr[ni] = *(const uint2*)(esw + n * AH_STRIDE + cb);
            }
            #pragma unroll
            for (int mi = 0; mi < 8; mi++) {
                int r = mi * 16 + g;
                uint2 alo = *(const uint2*)(as2 + r * AH_STRIDE + cb);
                uint2 ahi = *(const uint2*)(as2 + (r + 8) * AH_STRIDE + cb);
                #pragma unroll
                for (int ni = 0; ni < 2; ni++) {
                    asm volatile(
                        "mma.sync.aligned.m16n8k16.row.col.f32.f16.f16.f32 "
                        "{%0,%1,%2,%3}, {%4,%5,%6,%7}, {%8,%9}, {%0,%1,%2,%3};"
                        : "+f"(accr[mi][ni][0]), "+f"(accr[mi][ni][1]),
                          "+f"(accr[mi][ni][2]), "+f"(accr[mi][ni][3])
                        : "r"(alo.x), "r"(ahi.x), "r"(alo.y), "r"(ahi.y),
                          "r"(bfr[ni].x), "r"(bfr[ni].y));
                }
            }
        }

        // ---- epilogue: v-weighted tanh, h-sum fully warp-internal ----
        ull s2[2];
        s2[0] = pack2(0.f, 0.f);
        s2[1] = pack2(0.f, 0.f);
        #pragma unroll
        for (int mi = 0; mi < 8; mi++) {
            int h0 = mi * 16 + g;
            ull hxa = pack2(hxs[h0], hxs[h0]);
            ull hxb = pack2(hxs[h0 + 8], hxs[h0 + 8]);
            ull va  = pack2(vps[h0], vps[h0]);
            ull vb  = pack2(vps[h0 + 8], vps[h0 + 8]);
            #pragma unroll
            for (int ni = 0; ni < 2; ni++) {
                ull ya = add2(pack2(accr[mi][ni][0], accr[mi][ni][1]), hxa);
                ull yb = add2(pack2(accr[mi][ni][2], accr[mi][ni][3]), hxb);
                if (mi < 4) {
                    float l0, l1;
                    unpack2(ya, l0, l1);
                    s2[ni] = fma2(va, pack2(tanh_fast(l0), tanh_fast(l1)), s2[ni]);
                    unpack2(yb, l0, l1);
                    s2[ni] = fma2(vb, pack2(tanh_fast(l0), tanh_fast(l1)), s2[ni]);
                } else {
                    ull ua = mul2(ya, ya);
                    ull qa = fma2(ua, C7, C5);
                    qa = fma2(ua, qa, C3);
                    ull ta = fma2(mul2(ya, ua), qa, ya);
                    s2[ni] = fma2(va, ta, s2[ni]);

                    ull ub = mul2(yb, yb);
                    ull qb = fma2(ub, C7, C5);
                    qb = fma2(ub, qb, C3);
                    ull tb = fma2(mul2(yb, ub), qb, yb);
                    s2[ni] = fma2(vb, tb, s2[ni]);
                }
            }
        }

        // reduce over g (lane bits 2..4)
        float pl[2][2];
        unpack2(s2[0], pl[0][0], pl[0][1]);
        unpack2(s2[1], pl[1][0], pl[1][1]);
        #pragma unroll
        for (int off = 4; off < 32; off <<= 1)
            #pragma unroll
            for (int ni = 0; ni < 2; ni++)
                #pragma unroll
                for (int j = 0; j < 2; j++)
                    pl[ni][j] += __shfl_xor_sync(0xffffffff, pl[ni][j], off);

        if (g == 0) {
            // lane tc holds n-pair (ni*8 + 2tc, +1) -> STG.64
            ((float2*)(out + base))[tc]     = make_float2(pl[0][0], pl[0][1]);
            ((float2*)(out + base))[4 + tc] = make_float2(pl[1][0], pl[1][1]);
        }
        __syncwarp();   // all lanes done with esw/xsw before next overwrite
    }
}

// ---------------------------------------------------------------------------
// Kernel 2: softmax over N=1024 per batch, in place. Warp-shuffle reductions.
// ---------------------------------------------------------------------------
__global__ void k_softmax(float* __restrict__ out) {
    __shared__ float wred[8];
    __shared__ float bcast[2];
    int b = blockIdx.x;
    int t = threadIdx.x;
    int lane = t & 31, wid = t >> 5;
    float* row = out + b * 1024;
    float4 x = ((const float4*)row)[t];
    float m = fmaxf(fmaxf(x.x, x.y), fmaxf(x.z, x.w));
    #pragma unroll
    for (int o = 16; o > 0; o >>= 1)
        m = fmaxf(m, __shfl_xor_sync(0xffffffff, m, o));
    if (lane == 0) wred[wid] = m;
    __syncthreads();
    if (wid == 0) {
        float mm = wred[lane & 7];
        #pragma unroll
        for (int o = 4; o > 0; o >>= 1)
            mm = fmaxf(mm, __shfl_xor_sync(0xffffffff, mm, o));
        if (lane == 0) bcast[0] = mm;
    }
    __syncthreads();
    float M = bcast[0];
    float e0 = __expf(x.x - M);
    float e1 = __expf(x.y - M);
    float e2 = __expf(x.z - M);
    float e3 = __expf(x.w - M);
    float s = e0 + e1 + e2 + e3;
    #pragma unroll
    for (int o = 16; o > 0; o >>= 1)
        s += __shfl_xor_sync(0xffffffff, s, o);
    if (lane == 0) wred[wid] = s;
    __syncthreads();
    if (wid == 0) {
        float ss = wred[lane & 7];
        #pragma unroll
        for (int o = 4; o > 0; o >>= 1)
            ss += __shfl_xor_sync(0xffffffff, ss, o);
        if (lane == 0) bcast[1] = ss;
    }
    __syncthreads();
    float inv = 1.f / bcast[1];
    float4 r;
    r.x = e0 * inv; r.y = e1 * inv; r.z = e2 * inv; r.w = e3 * inv;
    ((float4*)row)[t] = r;
}

// ---------------------------------------------------------------------------
extern "C" void kernel_launch(void* const* d_in, const int* in_sizes, int n_in,
                              void* d_out, int out_size) {
    const float* nf     = (const float*)d_in[0];
    const float* Wemb   = (const float*)d_in[2];
    const float* bemb   = (const float*)d_in[3];
    const float* Wih    = (const float*)d_in[4];
    const float* bih    = (const float*)d_in[5];
    const float* bhh    = (const float*)d_in[7];
    const float* query  = (const float*)d_in[8];
    const float* Wattn  = (const float*)d_in[9];
    const float* vparam = (const float*)d_in[10];
    const float* Wval   = (const float*)d_in[11];
    const float* bval   = (const float*)d_in[12];
    float* out = (float*)d_out;

    static int smem_set = 0;
    const int smem_bytes = SM_FLOATS * 4;
    if (!smem_set) {
        cudaFuncSetAttribute(k_logits, cudaFuncAttributeMaxDynamicSharedMemorySize,
                             smem_bytes);
        smem_set = 1;
    }

    k_gates<<<32, 128>>>(Wih, bih, bhh, query);
    k_hxv<<<1, 128>>>(Wval, bval, out);
    k_logits<<<GRID_LOGITS, 128, smem_bytes>>>(nf, Wemb, bemb, Wattn, vparam, out);
    k_softmax<<<64, 256>>>(out);
}

// round 13
// speedup vs baseline: 2.0902x; 1.0994x over previous
#include <cuda_runtime.h>
#include <cuda_fp16.h>
#include <math.h>
#include <cstdint>

// Shapes: B=64, N=1024, F=4, H=128. BN = 65536 nodes.
// Output: pi [64,1024] then v [64,1] -> 65600 floats.
#define BN 65536
#define NT32 2048          // 32-node tiles
#define GRID_LOGITS 256    // x4 warps = 1024 -> exactly 2 tiles/warp

typedef unsigned long long ull;

__device__ float g_hx[128];

// ---------------- scalar helpers ----------------
__device__ __forceinline__ float tanh_fast(float x) {
    float r; asm("tanh.approx.f32 %0, %1;" : "=f"(r) : "f"(x)); return r;
}
// ---------------- packed f32x2 helpers ----------------
__device__ __forceinline__ ull pack2(float lo, float hi) {
    ull r; asm("mov.b64 %0, {%1, %2};" : "=l"(r) : "f"(lo), "f"(hi)); return r;
}
__device__ __forceinline__ void unpack2(ull p, float& lo, float& hi) {
    asm("mov.b64 {%0, %1}, %2;" : "=f"(lo), "=f"(hi) : "l"(p));
}
__device__ __forceinline__ ull fma2(ull a, ull b, ull c) {
    ull r; asm("fma.rn.f32x2 %0, %1, %2, %3;" : "=l"(r) : "l"(a), "l"(b), "l"(c)); return r;
}
__device__ __forceinline__ ull mul2(ull a, ull b) {
    ull r; asm("mul.rn.f32x2 %0, %1, %2;" : "=l"(r) : "l"(a), "l"(b)); return r;
}
__device__ __forceinline__ ull add2(ull a, ull b) {
    ull r; asm("add.rn.f32x2 %0, %1, %2;" : "=l"(r) : "l"(a), "l"(b)); return r;
}

// ---------------------------------------------------------------------------
// Kernel 0: fused gates + hx. 32 blocks x 128 threads; one warp per h index.
// Only gates i (row h), g (row 256+h), o (row 384+h) are needed (f*c0 = 0).
// ---------------------------------------------------------------------------
__global__ void k_gh(const float* __restrict__ Wih, const float* __restrict__ bih,
                     const float* __restrict__ bhh, const float* __restrict__ q) {
    int lane = threadIdx.x & 31, wid = threadIdx.x >> 5;
    int h = blockIdx.x * 4 + wid;
    float4 qv = __ldg((const float4*)q + lane);

    int rows[3] = {h, 256 + h, 384 + h};
    float acc[3];
    #pragma unroll
    for (int i = 0; i < 3; i++) {
        float4 wv = __ldg((const float4*)(Wih + rows[i] * 128) + lane);
        acc[i] = wv.x * qv.x + wv.y * qv.y + wv.z * qv.z + wv.w * qv.w;
    }
    #pragma unroll
    for (int o = 16; o > 0; o >>= 1)
        #pragma unroll
        for (int i = 0; i < 3; i++)
            acc[i] += __shfl_xor_sync(0xffffffff, acc[i], o);

    if (lane == 0) {
        float ig = acc[0] + bih[h] + bhh[h];
        float gg = acc[1] + bih[256 + h] + bhh[256 + h];
        float og = acc[2] + bih[384 + h] + bhh[384 + h];
        float si = 1.f / (1.f + __expf(-ig));
        float so = 1.f / (1.f + __expf(-og));
        float cx = si * tanh_fast(gg);
        g_hx[h] = so * tanh_fast(cx);
    }
}

// ---------------------------------------------------------------------------
// Kernel 1: logits, warp-autonomous 32-node x 128-h tiles.
// fp16 mma.sync m16n8k16 (mi=0..7, ni=0..3), fp32 accum. 2 tiles/warp.
// A fragments amortized over 2x the B work vs the 16-node tile.
// ---------------------------------------------------------------------------
#define AH_STRIDE 72
#define AS_OFF   0        // 128*72 half2 = 9216 float-slots
#define ES_OFF   9216     // 4 warps x 32*72 half2 = 9216 float-slots
#define XS_OFF   18432    // 4 warps x 32 float4 = 512 floats
#define HXS_OFF  18944    // 128
#define VPS_OFF  19072    // 128
#define SM_FLOATS 19200   // 76.8 KB/CTA, x2 = 153.6 KB

__global__ __launch_bounds__(128, 2)
void k_logits(const float* __restrict__ nf, const float* __restrict__ Wemb,
              const float* __restrict__ bemb, const float* __restrict__ Wattn,
              const float* __restrict__ vparam, float* __restrict__ out) {
    extern __shared__ float sm[];
    __half2* as2 = (__half2*)sm;              // [128][72]
    float* hxs   = sm + HXS_OFF;
    float* vps   = sm + VPS_OFF;

    int t = threadIdx.x;
    int lane = t & 31, w = t >> 5;
    int g = lane >> 2, tc = lane & 3;

    __half2* esw = (__half2*)(sm + ES_OFF) + w * (32 * AH_STRIDE);
    float4*  xsw = (float4*)(sm + XS_OFF) + w * 32;

    // ---- one-time staging: A = half2(W_attn), permuted k-pair columns ----
    for (int i = t * 4; i < 16384; i += 512) {
        float4 wv = *(const float4*)(Wattn + i);
        int h = i >> 7, k = i & 127;
        int k2 = k >> 1;
        int kb8 = k2 & ~7, j = k2 & 7;       // j in {0,2,4,6}
        int c1 = kb8 + ((j < 4) ? 2 * j : 2 * j - 7);
        as2[h * AH_STRIDE + c1]     = __floats2half2_rn(wv.x, wv.y);
        as2[h * AH_STRIDE + c1 + 2] = __floats2half2_rn(wv.z, wv.w);
    }
    hxs[t] = g_hx[t];
    vps[t] = vparam[t];

    // ---- per-lane embedding weights: TWO k2 pairs (lane, lane+32) ----
    ull w2[8], b2[2];
    int colL[2];
    #pragma unroll
    for (int p = 0; p < 2; p++) {
        int k2v = lane + p * 32;
        int kk = 2 * k2v;
        #pragma unroll
        for (int f = 0; f < 4; f++)
            w2[p * 4 + f] = pack2(Wemb[kk * 4 + f], Wemb[(kk + 1) * 4 + f]);
        b2[p] = pack2(bemb[kk], bemb[kk + 1]);
        int j = k2v & 7;
        colL[p] = (k2v & ~7) + ((j < 4) ? 2 * j : 2 * j - 7);
    }

    const ull C3 = pack2(-0.3333333333f, -0.3333333333f);
    const ull C5 = pack2(0.1333333333f, 0.1333333333f);
    const ull C7 = pack2(-0.0539682540f, -0.0539682540f);
    const __half2 hzero = __floats2half2_rn(0.f, 0.f);

    __syncthreads();   // as2 / hxs / vps ready (only block-wide sync)

    int gw = blockIdx.x * 4 + w;       // global warp id: 0..1023
    for (int tile = gw; tile < NT32; tile += GRID_LOGITS * 4) {
        int base = tile * 32;

        // ---- warp-private xs load (32 nodes) ----
        xsw[lane] = __ldg((const float4*)nf + (base + lane));
        __syncwarp();

        // ---- embedding: lane fills its two k2 columns for all 32 nodes ----
        #pragma unroll
        for (int n = 0; n < 32; n++) {
            float4 x = xsw[n];
            ull x0 = pack2(x.x, x.x), x1 = pack2(x.y, x.y);
            ull x2 = pack2(x.z, x.z), x3 = pack2(x.w, x.w);
            #pragma unroll
            for (int p = 0; p < 2; p++) {
                ull e = b2[p];
                e = fma2(x0, w2[p * 4 + 0], e);
                e = fma2(x1, w2[p * 4 + 1], e);
                e = fma2(x2, w2[p * 4 + 2], e);
                e = fma2(x3, w2[p * 4 + 3], e);
                float lo, hi;
                unpack2(e, lo, hi);
                esw[n * AH_STRIDE + colL[p]] =
                    __hmax2(__floats2half2_rn(lo, hi), hzero);
            }
        }
        __syncwarp();

        // ---- fp16 GEMM: warp tile 128h x 32n, K chunks of 16 ----
        float accr[8][4][4];
        #pragma unroll
        for (int mi = 0; mi < 8; mi++)
            #pragma unroll
            for (int ni = 0; ni < 4; ni++)
                #pragma unroll
                for (int j = 0; j < 4; j++) accr[mi][ni][j] = 0.f;

        #pragma unroll
        for (int kt = 0; kt < 8; kt++) {
            int cb = kt * 8 + 2 * tc;
            uint2 bfr[4];
            #pragma unroll
            for (int ni = 0; ni < 4; ni++) {
                int n = ni * 8 + g;
                bfr[ni] = *(const uint2*)(esw + n * AH_STRIDE + cb);
            }
            #pragma unroll
            for (int mi = 0; mi < 8; mi++) {
                int r = mi * 16 + g;
                uint2 alo = *(const uint2*)(as2 + r * AH_STRIDE + cb);
                uint2 ahi = *(const uint2*)(as2 + (r + 8) * AH_STRIDE + cb);
                #pragma unroll
                for (int ni = 0; ni < 4; ni++) {
                    asm volatile(
                        "mma.sync.aligned.m16n8k16.row.col.f32.f16.f16.f32 "
                        "{%0,%1,%2,%3}, {%4,%5,%6,%7}, {%8,%9}, {%0,%1,%2,%3};"
                        : "+f"(accr[mi][ni][0]), "+f"(accr[mi][ni][1]),
                          "+f"(accr[mi][ni][2]), "+f"(accr[mi][ni][3])
                        : "r"(alo.x), "r"(ahi.x), "r"(alo.y), "r"(ahi.y),
                          "r"(bfr[ni].x), "r"(bfr[ni].y));
                }
            }
        }

        // ---- epilogue: v-weighted tanh, h-sum fully warp-internal ----
        ull s2[4];
        #pragma unroll
        for (int ni = 0; ni < 4; ni++) s2[ni] = pack2(0.f, 0.f);
        #pragma unroll
        for (int mi = 0; mi < 8; mi++) {
            int h0 = mi * 16 + g;
            ull hxa = pack2(hxs[h0], hxs[h0]);
            ull hxb = pack2(hxs[h0 + 8], hxs[h0 + 8]);
            ull va  = pack2(vps[h0], vps[h0]);
            ull vb  = pack2(vps[h0 + 8], vps[h0 + 8]);
            #pragma unroll
            for (int ni = 0; ni < 4; ni++) {
                ull ya = add2(pack2(accr[mi][ni][0], accr[mi][ni][1]), hxa);
                ull yb = add2(pack2(accr[mi][ni][2], accr[mi][ni][3]), hxb);
                if (mi < 4) {
                    float l0, l1;
                    unpack2(ya, l0, l1);
                    s2[ni] = fma2(va, pack2(tanh_fast(l0), tanh_fast(l1)), s2[ni]);
                    unpack2(yb, l0, l1);
                    s2[ni] = fma2(vb, pack2(tanh_fast(l0), tanh_fast(l1)), s2[ni]);
                } else {
                    ull ua = mul2(ya, ya);
                    ull qa = fma2(ua, C7, C5);
                    qa = fma2(ua, qa, C3);
                    ull ta = fma2(mul2(ya, ua), qa, ya);
                    s2[ni] = fma2(va, ta, s2[ni]);

                    ull ub = mul2(yb, yb);
                    ull qb = fma2(ub, C7, C5);
                    qb = fma2(ub, qb, C3);
                    ull tb = fma2(mul2(yb, ub), qb, yb);
                    s2[ni] = fma2(vb, tb, s2[ni]);
                }
            }
        }

        // reduce over g (lane bits 2..4)
        float pl[4][2];
        #pragma unroll
        for (int ni = 0; ni < 4; ni++) unpack2(s2[ni], pl[ni][0], pl[ni][1]);
        #pragma unroll
        for (int off = 4; off < 32; off <<= 1)
            #pragma unroll
            for (int ni = 0; ni < 4; ni++)
                #pragma unroll
                for (int j = 0; j < 2; j++)
                    pl[ni][j] += __shfl_xor_sync(0xffffffff, pl[ni][j], off);

        if (g == 0) {
            #pragma unroll
            for (int ni = 0; ni < 4; ni++)
                ((float2*)(out + base))[ni * 4 + tc] =
                    make_float2(pl[ni][0], pl[ni][1]);
        }
        __syncwarp();   // all lanes done with esw/xsw before next overwrite
    }
}

// ---------------------------------------------------------------------------
// Kernel 2: softmax over N=1024 per batch (blocks 0..63) + v output (block 64).
// ---------------------------------------------------------------------------
__global__ void k_softmax(const float* __restrict__ Wval,
                          const float* __restrict__ bval,
                          float* __restrict__ out) {
    __shared__ float wred[8];
    __shared__ float bcast[2];
    int b = blockIdx.x;
    int t = threadIdx.x;
    int lane = t & 31, wid = t >> 5;

    if (b == 64) {
        if (wid == 0) {
            float s = g_hx[lane] * Wval[lane]
                    + g_hx[32 + lane] * Wval[32 + lane]
                    + g_hx[64 + lane] * Wval[64 + lane]
                    + g_hx[96 + lane] * Wval[96 + lane];
            #pragma unroll
            for (int o = 16; o > 0; o >>= 1)
                s += __shfl_xor_sync(0xffffffff, s, o);
            float v = s + bval[0];
            out[BN + lane] = v;
            out[BN + 32 + lane] = v;
        }
        return;
    }

    float* row = out + b * 1024;
    float4 x = ((const float4*)row)[t];
    float m = fmaxf(fmaxf(x.x, x.y), fmaxf(x.z, x.w));
    #pragma unroll
    for (int o = 16; o > 0; o >>= 1)
        m = fmaxf(m, __shfl_xor_sync(0xffffffff, m, o));
    if (lane == 0) wred[wid] = m;
    __syncthreads();
    if (wid == 0) {
        float mm = wred[lane & 7];
        #pragma unroll
        for (int o = 4; o > 0; o >>= 1)
            mm = fmaxf(mm, __shfl_xor_sync(0xffffffff, mm, o));
        if (lane == 0) bcast[0] = mm;
    }
    __syncthreads();
    float M = bcast[0];
    float e0 = __expf(x.x - M);
    float e1 = __expf(x.y - M);
    float e2 = __expf(x.z - M);
    float e3 = __expf(x.w - M);
    float s = e0 + e1 + e2 + e3;
    #pragma unroll
    for (int o = 16; o > 0; o >>= 1)
        s += __shfl_xor_sync(0xffffffff, s, o);
    if (lane == 0) wred[wid] = s;
    __syncthreads();
    if (wid == 0) {
        float ss = wred[lane & 7];
        #pragma unroll
        for (int o = 4; o > 0; o >>= 1)
            ss += __shfl_xor_sync(0xffffffff, ss, o);
        if (lane == 0) bcast[1] = ss;
    }
    __syncthreads();
    float inv = 1.f / bcast[1];
    float4 r;
    r.x = e0 * inv; r.y = e1 * inv; r.z = e2 * inv; r.w = e3 * inv;
    ((float4*)row)[t] = r;
}

// ---------------------------------------------------------------------------
extern "C" void kernel_launch(void* const* d_in, const int* in_sizes, int n_in,
                              void* d_out, int out_size) {
    const float* nf     = (const float*)d_in[0];
    const float* Wemb   = (const float*)d_in[2];
    const float* bemb   = (const float*)d_in[3];
    const float* Wih    = (const float*)d_in[4];
    const float* bih    = (const float*)d_in[5];
    const float* bhh    = (const float*)d_in[7];
    const float* query  = (const float*)d_in[8];
    const float* Wattn  = (const float*)d_in[9];
    const float* vparam = (const float*)d_in[10];
    const float* Wval   = (const float*)d_in[11];
    const float* bval   = (const float*)d_in[12];
    float* out = (float*)d_out;

    static int smem_set = 0;
    const int smem_bytes = SM_FLOATS * 4;
    if (!smem_set) {
        cudaFuncSetAttribute(k_logits, cudaFuncAttributeMaxDynamicSharedMemorySize,
                             smem_bytes);
        smem_set = 1;
    }

    k_gh<<<32, 128>>>(Wih, bih, bhh, query);
    k_logits<<<GRID_LOGITS, 128, smem_bytes>>>(nf, Wemb, bemb, Wattn, vparam, out);
    k_softmax<<<65, 256>>>(Wval, bval, out);
}